// round 16
// baseline (speedup 1.0000x reference)
#include <cuda_runtime.h>
#include <cuda_fp16.h>
#include <math.h>
#include <stdint.h>

#define NT 256
#define TB 128
#define KDIM 160
#define RS 168           // k-stride (elements)

// smem byte offsets
#define OFF_A   0                 // fp16 [128][168] = 43008
#define OFF_B   43008             // [buf][64][168] fp16 : 2 x 21504  (pre-barrier: U scratch)
#define OFF_QIN 86016             // float [2][128][4]
#define OFF_B1  90112             // float [2][256]
#define OFF_W2F 92160             // uint2 [2][16][32] packed W2 B-frags = 8192
#define OFF_B2  100352            // float [2][4]
#define OFF_A16 100384            // float [2][16][16] quadratic-form matrices
#define OFF_PP  102432
#define SMEM_BYTES 102448

#define BCH  21504       // bytes per N=64 chunk (64 x 168 x 2B)
#define GRID_P 296       // persistent grid (148 SMs x 2 CTAs; all co-resident)

// W1 as fp16, [br][n][RS]
__device__ __align__(16) __half g_W1h[2][256][RS];
// grid-barrier ticket counter (monotonic across graph replays)
__device__ unsigned long long g_ctr;

__device__ __forceinline__ uint32_t smem_u32(const void* p) {
    uint32_t a;
    asm("{ .reg .u64 t; cvta.to.shared.u64 t, %1; cvt.u32.u64 %0, t; }" : "=r"(a) : "l"(p));
    return a;
}
__device__ __forceinline__ void mma_f16(float (&d)[4], const uint32_t (&a)[4],
                                        uint32_t b0, uint32_t b1) {
    asm volatile(
        "mma.sync.aligned.m16n8k16.row.col.f32.f16.f16.f32 "
        "{%0,%1,%2,%3}, {%4,%5,%6,%7}, {%8,%9}, {%0,%1,%2,%3};"
        : "+f"(d[0]), "+f"(d[1]), "+f"(d[2]), "+f"(d[3])
        : "r"(a[0]), "r"(a[1]), "r"(a[2]), "r"(a[3]), "r"(b0), "r"(b1));
}
__device__ __forceinline__ void mma_f16u(float (&d)[4], uint32_t a0, uint32_t a1,
                                         uint32_t a2, uint32_t a3,
                                         uint32_t b0, uint32_t b1) {
    asm volatile(
        "mma.sync.aligned.m16n8k16.row.col.f32.f16.f16.f32 "
        "{%0,%1,%2,%3}, {%4,%5,%6,%7}, {%8,%9}, {%0,%1,%2,%3};"
        : "+f"(d[0]), "+f"(d[1]), "+f"(d[2]), "+f"(d[3])
        : "r"(a0), "r"(a1), "r"(a2), "r"(a3), "r"(b0), "r"(b1));
}
__device__ __forceinline__ void ldsm4(uint32_t (&r)[4], uint32_t addr) {
    asm volatile("ldmatrix.sync.aligned.m8n8.x4.shared.b16 {%0,%1,%2,%3}, [%4];"
        : "=r"(r[0]), "=r"(r[1]), "=r"(r[2]), "=r"(r[3]) : "r"(addr));
}
__device__ __forceinline__ uint32_t h2u(float a, float b) {
    __half2 h = __floats2half2_rn(a, b);
    return *(uint32_t*)&h;
}
#define CPA16(dst, src) asm volatile("cp.async.cg.shared.global [%0], [%1], 16;" :: "r"(dst), "l"(src))
#define CPA_COMMIT()    asm volatile("cp.async.commit_group;")
#define CPA_WAIT1()     asm volatile("cp.async.wait_group 1;")
#define CPA_WAIT0()     asm volatile("cp.async.wait_group 0;")

// ---------------- quantum gates on 16-amplitude register state ----------------
template<int M>
__device__ __forceinline__ void g_ry(float (&ar)[16], float (&ai)[16], float c, float s) {
#pragma unroll
    for (int i = 0; i < 16; i++) if (!(i & M)) {
        const int j = i | M;
        float xr = ar[i], xi = ai[i], yr = ar[j], yi = ai[j];
        ar[i] = c * xr - s * yr;  ai[i] = c * xi - s * yi;
        ar[j] = s * xr + c * yr;  ai[j] = s * xi + c * yi;
    }
}
template<int M>
__device__ __forceinline__ void g_rx(float (&ar)[16], float (&ai)[16], float c, float s) {
#pragma unroll
    for (int i = 0; i < 16; i++) if (!(i & M)) {
        const int j = i | M;
        float xr = ar[i], xi = ai[i], yr = ar[j], yi = ai[j];
        ar[i] = c * xr + s * yi;   ai[i] = c * xi - s * yr;
        ar[j] = s * xi + c * yr;   ai[j] = -s * xr + c * yi;
    }
}
template<int M>
__device__ __forceinline__ void g_rz(float (&ar)[16], float (&ai)[16], float c, float s) {
#pragma unroll
    for (int i = 0; i < 16; i++) if (!(i & M)) {
        const int j = i | M;
        float xr = ar[i], xi = ai[i], yr = ar[j], yi = ai[j];
        ar[i] = c * xr + s * xi;   ai[i] = c * xi - s * xr;
        ar[j] = c * yr - s * yi;   ai[j] = c * yi + s * yr;
    }
}
template<int MC, int MT>
__device__ __forceinline__ void g_cnot(float (&ar)[16], float (&ai)[16]) {
#pragma unroll
    for (int i = 0; i < 16; i++) if ((i & MC) && !(i & MT)) {
        const int j = i | MT;
        float tr = ar[i]; ar[i] = ar[j]; ar[j] = tr;
        float ti = ai[i]; ai[i] = ai[j]; ai[j] = ti;
    }
}

// ---------------- main kernel (persistent, fused prep + grid barrier) ----------------
__global__ __launch_bounds__(NT, 2)
void qmain(const float* __restrict__ state, const float* __restrict__ action,
           const float* __restrict__ W1a, const float* __restrict__ W1b,
           const float* __restrict__ b1a, const float* __restrict__ W2a, const float* __restrict__ b2a,
           const float* __restrict__ b1b, const float* __restrict__ W2b, const float* __restrict__ b2b,
           const float* __restrict__ qwa, const float* __restrict__ qwb,
           const float* __restrict__ pwa, const float* __restrict__ pba,
           const float* __restrict__ pwb, const float* __restrict__ pbb,
           float* __restrict__ out, int Btot)
{
    extern __shared__ __align__(16) unsigned char smp[];
    float* smf = (float*)smp;
    __half* Ah = (__half*)(smp + OFF_A);
    float* qin = smf + OFF_QIN / 4;
    const uint32_t smb = smem_u32(smp);

    const int tid = threadIdx.x;
    const int lane = tid & 31, w = tid >> 5;
    const int gid = lane >> 2, tig = lane & 3;
    const int wm = w & 3, wn = w >> 2;
    const int m0 = wm * 32, n0 = wn * 32;
    const int ntiles = Btot / TB;
    const int G = gridDim.x;
    const int bid = blockIdx.x;

    // balanced contiguous partition
    const int base = ntiles / G, rem = ntiles % G;
    const int cnt = base + (bid < rem ? 1 : 0);
    const int start = bid * base + (bid < rem ? bid : rem);

    // ---- fused prep (1): this CTA's slice of W1 -> fp16 global image ----
    {
        const int g = bid * NT + tid;          // 0 .. G*NT-1
        if (g < 20480) {
            const int br = g / 10240;
            const int r2 = g % 10240;
            const int n = r2 / 40, k4 = r2 % 40;
            const float4 v = *(const float4*)((br ? W1b : W1a) + (size_t)n * KDIM + k4 * 4);
            __half2* dst = (__half2*)&g_W1h[br][n][k4 * 4];
            dst[0] = __floats2half2_rn(v.x, v.y);
            dst[1] = __floats2half2_rn(v.z, v.w);
        }
    }

    // ---- fused prep (2): fixed-circuit unitary into smem scratch (B-buf area) ----
    float* Ur = (float*)(smp + OFF_B);          // [2][16][16]
    float* Ui = Ur + 512;                        // [2][16][16]
    if (tid < 32) {
        const int br = tid >> 4, col = tid & 15;
        const float* qw = br ? qwb : qwa;
        float trc[24], trs[24];
#pragma unroll
        for (int g = 0; g < 24; g++) sincosf(0.5f * qw[g], &trs[g], &trc[g]);
        float ar[16], ai[16];
#pragma unroll
        for (int i = 0; i < 16; i++) { ar[i] = (i == col) ? 1.f : 0.f; ai[i] = 0.f; }
#pragma unroll
        for (int l = 0; l < 2; l++) {
            const int lb = l * 12;
            g_rx<8>(ar, ai, trc[lb + 0],  trs[lb + 0]);
            g_ry<8>(ar, ai, trc[lb + 1],  trs[lb + 1]);
            g_rz<8>(ar, ai, trc[lb + 2],  trs[lb + 2]);
            g_rx<4>(ar, ai, trc[lb + 3],  trs[lb + 3]);
            g_ry<4>(ar, ai, trc[lb + 4],  trs[lb + 4]);
            g_rz<4>(ar, ai, trc[lb + 5],  trs[lb + 5]);
            g_rx<2>(ar, ai, trc[lb + 6],  trs[lb + 6]);
            g_ry<2>(ar, ai, trc[lb + 7],  trs[lb + 7]);
            g_rz<2>(ar, ai, trc[lb + 8],  trs[lb + 8]);
            g_rx<1>(ar, ai, trc[lb + 9],  trs[lb + 9]);
            g_ry<1>(ar, ai, trc[lb + 10], trs[lb + 10]);
            g_rz<1>(ar, ai, trc[lb + 11], trs[lb + 11]);
            g_cnot<8, 4>(ar, ai);
            g_cnot<4, 2>(ar, ai);
            g_cnot<2, 1>(ar, ai);
            g_cnot<1, 8>(ar, ai);
        }
#pragma unroll
        for (int k = 0; k < 16; k++) {
            Ur[(br << 8) + k * 16 + col] = ar[k];
            Ui[(br << 8) + k * 16 + col] = ai[k];
        }
    }

    // ---- params into smem ----
    for (int i = tid; i < 512; i += NT)
        smf[OFF_B1 / 4 + i] = ((i >> 8) ? b1b : b1a)[i & 255];
    for (int i = tid; i < 1024; i += NT) {
        const int br = i >> 9, g = (i >> 5) & 15, ln = i & 31;
        const int gq = ln >> 2, gt = ln & 3;
        const int kc = g * 16 + 2 * gt;
        const float* W2 = br ? W2b : W2a;
        uint32_t r0 = 0, r1 = 0;
        if (gq < 4) {
            r0 = h2u(W2[gq * 256 + kc],     W2[gq * 256 + kc + 1]);
            r1 = h2u(W2[gq * 256 + kc + 8], W2[gq * 256 + kc + 9]);
        }
        ((uint2*)(smp + OFF_W2F))[i] = make_uint2(r0, r1);
    }
    if (tid < 8)  smf[OFF_B2 / 4 + tid] = ((tid >> 2) ? b2b : b2a)[tid & 3];
    if (tid < 4)
        smf[OFF_PP / 4 + tid] = (tid == 0) ? pwa[0] : (tid == 1) ? pba[0]
                               : (tid == 2) ? pwb[0] : pbb[0];
    for (int i = tid; i < 1024; i += NT) qin[i] = 0.f;

    __syncthreads();   // U scratch ready

    // ---- fused prep (3): quadratic-form A = Re(U^T Z0 U) into smem ----
#pragma unroll
    for (int e = 0; e < 2; e++) {
        const int idx = e * NT + tid;          // 0..511
        const int br = idx >> 8, r2 = idx & 255;
        const int i = r2 >> 4, j = r2 & 15;
        float s = 0.f;
        const float* ur = Ur + (br << 8);
        const float* ui = Ui + (br << 8);
#pragma unroll
        for (int k = 0; k < 16; k++) {
            const float z = (k & 8) ? -1.f : 1.f;
            s += z * (ur[k * 16 + i] * ur[k * 16 + j] + ui[k * 16 + i] * ui[k * 16 + j]);
        }
        smf[OFF_A16 / 4 + idx] = s;
    }

    // ---- first-tile A conversion (independent of W1 image) ----
    {
        const int rowg0 = start * TB;
        const int r = tid >> 1, hf = tid & 1;
        const float* srow = state  + (size_t)(rowg0 + r) * 128;
        const float* arow = action + (size_t)(rowg0 + r) * 32;
#pragma unroll 5
        for (int i = 0; i < 20; i++) {
            const int k = hf * 80 + i * 4;
            const float4 v = (k < 128) ? *(const float4*)(srow + k)
                                       : *(const float4*)(arow + (k - 128));
            *(__half2*)(Ah + r * RS + k)     = __floats2half2_rn(v.x, v.y);
            *(__half2*)(Ah + r * RS + k + 2) = __floats2half2_rn(v.z, v.w);
        }
    }
    __syncthreads();   // A16 done reading scratch; A tile ready

    // ---- grid-wide ticket barrier: W1 fp16 image complete ----
    if (tid == 0) {
        __threadfence();
        const unsigned long long t = atomicAdd(&g_ctr, 1ULL);
        const unsigned long long target =
            (t / (unsigned long long)G + 1ULL) * (unsigned long long)G;
        while (true) {
            unsigned long long v;
            asm volatile("ld.acquire.gpu.u64 %0, [%1];" : "=l"(v) : "l"(&g_ctr));
            if (v >= target) break;
            __nanosleep(64);
        }
    }
    __syncthreads();

    // ---- kick off B load for pass 0 (buf 0) ----
    {
        const char* sH = (const char*)&g_W1h[0][0][0];
        for (int i = tid; i < BCH / 16; i += NT)
            CPA16(smb + OFF_B + i * 16, sH + i * 16);
        CPA_COMMIT();
    }

    // ---- ldmatrix byte-address bases ----
    const uint32_t aB0 = smb + OFF_A
        + (uint32_t)((m0 + (lane & 15)) * RS + 8 * (lane >> 4)) * 2;
    const uint32_t aB1 = aB0 + 16u * RS * 2;
    const uint32_t bO0 = (uint32_t)((n0 + 8 * (lane >> 4) + (lane & 7)) * RS
                                    + 8 * ((lane >> 3) & 1)) * 2;
    const uint32_t bO1 = bO0 + 16u * RS * 2;

    // q partial accumulators (tensor-core epilogue), per mf fragment
    float qacc[2][4];
#pragma unroll
    for (int mf = 0; mf < 2; mf++)
#pragma unroll
        for (int c = 0; c < 4; c++) qacc[mf][c] = 0.f;

    // ================= persistent tile loop =================
    for (int t = 0; t < cnt; t++) {
        const int tile = start + t;
        const int rowg0 = tile * TB;
        const bool last_tile = (t == cnt - 1);

        // ---- x -> fp16 A tile (tile 0 already converted pre-barrier) ----
        if (t > 0) {
            const int r = tid >> 1, hf = tid & 1;
            const float* srow = state  + (size_t)(rowg0 + r) * 128;
            const float* arow = action + (size_t)(rowg0 + r) * 32;
#pragma unroll 5
            for (int i = 0; i < 20; i++) {
                const int k = hf * 80 + i * 4;
                const float4 v = (k < 128) ? *(const float4*)(srow + k)
                                           : *(const float4*)(arow + (k - 128));
                *(__half2*)(Ah + r * RS + k)     = __floats2half2_rn(v.x, v.y);
                *(__half2*)(Ah + r * RS + k + 2) = __floats2half2_rn(v.z, v.w);
            }
        }
        __syncthreads();   // A ready / qin reset visible

#pragma unroll 1
        for (int pass = 0; pass < 8; pass++) {
            const int br = pass >> 2, chunk = pass & 3;
            const int nbase = chunk * 64;
            const int buf = pass & 1;

            // prefetch next pass ((pass+1) mod 8 — tile-invariant sequence)
            if (!(last_tile && pass == 7)) {
                const int pN = (pass + 1) & 7;
                const char* sH = (const char*)&g_W1h[pN >> 2][(pN & 3) * 64][0];
                const uint32_t dst = smb + OFF_B + (uint32_t)(pN & 1) * BCH;
                for (int i = tid; i < BCH / 16; i += NT)
                    CPA16(dst + i * 16, sH + i * 16);
                CPA_COMMIT();
                CPA_WAIT1();
            } else {
                CPA_WAIT0();
            }
            __syncthreads();

            const uint32_t bB = smb + OFF_B + (uint32_t)buf * BCH;

            float acc[2][4][4];
#pragma unroll
            for (int mf = 0; mf < 2; mf++)
#pragma unroll
                for (int nf = 0; nf < 4; nf++)
#pragma unroll
                    for (int c = 0; c < 4; c++) acc[mf][nf][c] = 0.f;

#pragma unroll
            for (int ks = 0; ks < 10; ks++) {
                const uint32_t kb = (uint32_t)(ks * 32);   // 16 elem * 2B
                uint32_t af[2][4], bf[2][4];
                ldsm4(af[0], aB0 + kb);
                ldsm4(af[1], aB1 + kb);
                ldsm4(bf[0], bB + bO0 + kb);
                ldsm4(bf[1], bB + bO1 + kb);
#pragma unroll
                for (int g = 0; g < 2; g++)
#pragma unroll
                    for (int h = 0; h < 2; h++)
#pragma unroll
                        for (int mf = 0; mf < 2; mf++)
                            mma_f16(acc[mf][g * 2 + h], af[mf], bf[g][h * 2], bf[g][h * 2 + 1]);
            }

            // ---- tensor-core epilogue: bias+relu -> fp16 frags -> MMA vs W2 frags ----
            {
                const float2* b1v = (const float2*)(smf + OFF_B1 / 4 + br * 256);
                const uint2* w2f = (const uint2*)(smp + OFF_W2F);
                const int gbase = (nbase + n0) >> 4;
                const uint2 bfA = w2f[(((br << 4) + gbase) << 5) + lane];
                const uint2 bfB = w2f[(((br << 4) + gbase + 1) << 5) + lane];
#pragma unroll
                for (int ks = 0; ks < 2; ks++) {
                    const int nfa = ks * 2, nfb = nfa + 1;
                    const float2 bba = b1v[((nbase + n0 + nfa * 8) >> 1) + tig];
                    const float2 bbb = b1v[((nbase + n0 + nfb * 8) >> 1) + tig];
                    const uint2 bfr = ks ? bfB : bfA;
#pragma unroll
                    for (int mf = 0; mf < 2; mf++) {
                        const uint32_t a0 = h2u(fmaxf(acc[mf][nfa][0] + bba.x, 0.f),
                                                fmaxf(acc[mf][nfa][1] + bba.y, 0.f));
                        const uint32_t a1 = h2u(fmaxf(acc[mf][nfa][2] + bba.x, 0.f),
                                                fmaxf(acc[mf][nfa][3] + bba.y, 0.f));
                        const uint32_t a2 = h2u(fmaxf(acc[mf][nfb][0] + bbb.x, 0.f),
                                                fmaxf(acc[mf][nfb][1] + bbb.y, 0.f));
                        const uint32_t a3 = h2u(fmaxf(acc[mf][nfb][2] + bbb.x, 0.f),
                                                fmaxf(acc[mf][nfb][3] + bbb.y, 0.f));
                        mma_f16u(qacc[mf], a0, a1, a2, a3, bfr.x, bfr.y);
                    }
                }
            }

            // flush q partials at branch boundary
            if (chunk == 3) {
                if (tig < 2) {
                    const int qb = 2 * tig;
#pragma unroll
                    for (int mf = 0; mf < 2; mf++) {
                        float* q0 = qin + ((br << 7) + m0 + mf * 16 + gid) * 4 + qb;
                        float* q1 = qin + ((br << 7) + m0 + mf * 16 + gid + 8) * 4 + qb;
                        atomicAdd(q0,     qacc[mf][0]);
                        atomicAdd(q0 + 1, qacc[mf][1]);
                        atomicAdd(q1,     qacc[mf][2]);
                        atomicAdd(q1 + 1, qacc[mf][3]);
                    }
                }
#pragma unroll
                for (int mf = 0; mf < 2; mf++)
#pragma unroll
                    for (int c = 0; c < 4; c++) qacc[mf][c] = 0.f;
            }

            __syncthreads();   // all reads of buf done before overwrite
        }

        // ---- quadratic-form epilogue: 1 row/thread, 128 rows x 2 branches ----
        {
            const int br = tid >> 7, row = tid & 127;
            const float* b2s = smf + OFF_B2 / 4 + br * 4;
            const float* Ab = smf + OFF_A16 / 4 + br * 256;
            const float pw = smf[OFF_PP / 4 + br * 2];
            const float pb = smf[OFF_PP / 4 + br * 2 + 1];
            float* qv = qin + ((br << 7) + row) * 4;

            float c[4], s[4];
#pragma unroll
            for (int q = 0; q < 4; q++) {
                sincosf(0.5f * (qv[q] + b2s[q]), &s[q], &c[q]);
                qv[q] = 0.f;    // reset for next tile (ordered by next A-sync)
            }

            float p01[4] = {c[0] * c[1], c[0] * s[1], s[0] * c[1], s[0] * s[1]};
            float p23[4] = {c[2] * c[3], c[2] * s[3], s[2] * c[3], s[2] * s[3]};
            float v[16];
#pragma unroll
            for (int hi = 0; hi < 4; hi++)
#pragma unroll
                for (int lo = 0; lo < 4; lo++)
                    v[hi * 4 + lo] = p01[hi] * p23[lo];

            float ev = 0.f;
#pragma unroll
            for (int i = 0; i < 16; i++) {
                const float4* Ar = (const float4*)(Ab + i * 16);
                float wi = 0.f;
#pragma unroll
                for (int j4 = 0; j4 < 4; j4++) {
                    const float4 a4 = Ar[j4];
                    wi = fmaf(a4.x, v[j4 * 4 + 0], wi);
                    wi = fmaf(a4.y, v[j4 * 4 + 1], wi);
                    wi = fmaf(a4.z, v[j4 * 4 + 2], wi);
                    wi = fmaf(a4.w, v[j4 * 4 + 3], wi);
                }
                ev = fmaf(v[i], wi, ev);
            }
            out[(size_t)br * Btot + rowg0 + row] = fmaf(ev, pw, pb);
        }
    }
}

extern "C" void kernel_launch(void* const* d_in, const int* in_sizes, int n_in,
                              void* d_out, int out_size)
{
    const int Btot = in_sizes[0] / 128;
    const int ntiles = Btot / TB;
    const int grid = (ntiles < GRID_P) ? ntiles : GRID_P;
    static bool attr_set = false;
    if (!attr_set) {
        cudaFuncSetAttribute(qmain, cudaFuncAttributeMaxDynamicSharedMemorySize, SMEM_BYTES);
        attr_set = true;
    }
    qmain<<<grid, NT, SMEM_BYTES>>>(
        (const float*)d_in[0],  (const float*)d_in[1],
        (const float*)d_in[2],  (const float*)d_in[6],
        (const float*)d_in[3],  (const float*)d_in[4],  (const float*)d_in[5],
        (const float*)d_in[7],  (const float*)d_in[8],  (const float*)d_in[9],
        (const float*)d_in[10], (const float*)d_in[11],
        (const float*)d_in[12], (const float*)d_in[13],
        (const float*)d_in[14], (const float*)d_in[15],
        (float*)d_out, Btot);
}

// round 17
// speedup vs baseline: 1.0225x; 1.0225x over previous
#include <cuda_runtime.h>
#include <cuda_fp16.h>
#include <math.h>
#include <stdint.h>

#define NT 256
#define TB 128
#define KDIM 160
#define RS 168           // k-stride (elements)

// smem byte offsets
#define OFF_A   0                 // fp16 [128][168] = 43008
#define OFF_B   43008             // [buf][64][168] fp16 : 2 x 21504
#define OFF_QIN 86016             // float [2][128][4]
#define OFF_B1  90112             // float [2][256]
#define OFF_W2F 92160             // uint2 [2][16][32] packed W2 B-frags = 8192
#define OFF_B2  100352            // float [2][4]
#define OFF_A16 100384            // float [2][16][16] quadratic-form matrices
#define OFF_PP  102432
#define SMEM_BYTES 102448

#define BCH  21504       // bytes per N=64 chunk (64 x 168 x 2B)
#define GRID_P 296       // persistent grid (148 SMs x 2 CTAs)

// W1 as fp16, [br][n][RS]
__device__ __align__(16) __half g_W1h[2][256][RS];
// quadratic-form matrices A = Re(U^T Z0 U), [br][i][j]
__device__ float g_A[2][16][16];

__device__ __forceinline__ uint32_t smem_u32(const void* p) {
    uint32_t a;
    asm("{ .reg .u64 t; cvta.to.shared.u64 t, %1; cvt.u32.u64 %0, t; }" : "=r"(a) : "l"(p));
    return a;
}
// fp16-accumulator HMMA: D/C packed half2 x2
__device__ __forceinline__ void mma_f16h(uint32_t (&d)[2], const uint32_t (&a)[4],
                                         uint32_t b0, uint32_t b1) {
    asm volatile(
        "mma.sync.aligned.m16n8k16.row.col.f16.f16.f16.f16 "
        "{%0,%1}, {%2,%3,%4,%5}, {%6,%7}, {%0,%1};"
        : "+r"(d[0]), "+r"(d[1])
        : "r"(a[0]), "r"(a[1]), "r"(a[2]), "r"(a[3]), "r"(b0), "r"(b1));
}
// fp32-accumulator HMMA (W2 epilogue)
__device__ __forceinline__ void mma_f16u(float (&d)[4], uint32_t a0, uint32_t a1,
                                         uint32_t a2, uint32_t a3,
                                         uint32_t b0, uint32_t b1) {
    asm volatile(
        "mma.sync.aligned.m16n8k16.row.col.f32.f16.f16.f32 "
        "{%0,%1,%2,%3}, {%4,%5,%6,%7}, {%8,%9}, {%0,%1,%2,%3};"
        : "+f"(d[0]), "+f"(d[1]), "+f"(d[2]), "+f"(d[3])
        : "r"(a0), "r"(a1), "r"(a2), "r"(a3), "r"(b0), "r"(b1));
}
__device__ __forceinline__ void ldsm4(uint32_t (&r)[4], uint32_t addr) {
    asm volatile("ldmatrix.sync.aligned.m8n8.x4.shared.b16 {%0,%1,%2,%3}, [%4];"
        : "=r"(r[0]), "=r"(r[1]), "=r"(r[2]), "=r"(r[3]) : "r"(addr));
}
__device__ __forceinline__ uint32_t h2u(float a, float b) {
    __half2 h = __floats2half2_rn(a, b);
    return *(uint32_t*)&h;
}
#define CPA16(dst, src) asm volatile("cp.async.cg.shared.global [%0], [%1], 16;" :: "r"(dst), "l"(src))
#define CPA_COMMIT()    asm volatile("cp.async.commit_group;")
#define CPA_WAIT1()     asm volatile("cp.async.wait_group 1;")
#define CPA_WAIT0()     asm volatile("cp.async.wait_group 0;")

// ---------------- quantum gates on 16-amplitude register state ----------------
template<int M>
__device__ __forceinline__ void g_ry(float (&ar)[16], float (&ai)[16], float c, float s) {
#pragma unroll
    for (int i = 0; i < 16; i++) if (!(i & M)) {
        const int j = i | M;
        float xr = ar[i], xi = ai[i], yr = ar[j], yi = ai[j];
        ar[i] = c * xr - s * yr;  ai[i] = c * xi - s * yi;
        ar[j] = s * xr + c * yr;  ai[j] = s * xi + c * yi;
    }
}
template<int M>
__device__ __forceinline__ void g_rx(float (&ar)[16], float (&ai)[16], float c, float s) {
#pragma unroll
    for (int i = 0; i < 16; i++) if (!(i & M)) {
        const int j = i | M;
        float xr = ar[i], xi = ai[i], yr = ar[j], yi = ai[j];
        ar[i] = c * xr + s * yi;   ai[i] = c * xi - s * yr;
        ar[j] = s * xi + c * yr;   ai[j] = -s * xr + c * yi;
    }
}
template<int M>
__device__ __forceinline__ void g_rz(float (&ar)[16], float (&ai)[16], float c, float s) {
#pragma unroll
    for (int i = 0; i < 16; i++) if (!(i & M)) {
        const int j = i | M;
        float xr = ar[i], xi = ai[i], yr = ar[j], yi = ai[j];
        ar[i] = c * xr + s * xi;   ai[i] = c * xi - s * xr;
        ar[j] = c * yr - s * yi;   ai[j] = c * yi + s * yr;
    }
}
template<int MC, int MT>
__device__ __forceinline__ void g_cnot(float (&ar)[16], float (&ai)[16]) {
#pragma unroll
    for (int i = 0; i < 16; i++) if ((i & MC) && !(i & MT)) {
        const int j = i | MT;
        float tr = ar[i]; ar[i] = ar[j]; ar[j] = tr;
        float ti = ai[i]; ai[i] = ai[j]; ai[j] = ti;
    }
}

// ---------------- merged prep: W1 -> fp16 (blocks 0..79) + circuit A (block 80) ----
__global__ void qpre(const float* __restrict__ W1a, const float* __restrict__ W1b,
                     const float* __restrict__ qwa, const float* __restrict__ qwb) {
    if (blockIdx.x < 80) {
        const int t = blockIdx.x * 256 + threadIdx.x;    // 0..20479
        const int br = t / 10240;
        const int rem = t % 10240;
        const int n = rem / 40, k4 = rem % 40;
        const float4 v = *(const float4*)((br ? W1b : W1a) + (size_t)n * KDIM + k4 * 4);
        __half2* dst = (__half2*)&g_W1h[br][n][k4 * 4];
        dst[0] = __floats2half2_rn(v.x, v.y);
        dst[1] = __floats2half2_rn(v.z, v.w);
        return;
    }
    // ---- block 80: fixed-circuit unitary -> quadratic form A (256 threads) ----
    __shared__ float Ur[2][16][16], Ui[2][16][16];   // [br][k][col]
    const int tid = threadIdx.x;
    if (tid < 32) {
        const int br = tid >> 4, col = tid & 15;
        const float* qw = br ? qwb : qwa;
        float trc[24], trs[24];
#pragma unroll
        for (int g = 0; g < 24; g++) sincosf(0.5f * qw[g], &trs[g], &trc[g]);
        float ar[16], ai[16];
#pragma unroll
        for (int i = 0; i < 16; i++) { ar[i] = (i == col) ? 1.f : 0.f; ai[i] = 0.f; }
#pragma unroll
        for (int l = 0; l < 2; l++) {
            const int lb = l * 12;
            g_rx<8>(ar, ai, trc[lb + 0],  trs[lb + 0]);
            g_ry<8>(ar, ai, trc[lb + 1],  trs[lb + 1]);
            g_rz<8>(ar, ai, trc[lb + 2],  trs[lb + 2]);
            g_rx<4>(ar, ai, trc[lb + 3],  trs[lb + 3]);
            g_ry<4>(ar, ai, trc[lb + 4],  trs[lb + 4]);
            g_rz<4>(ar, ai, trc[lb + 5],  trs[lb + 5]);
            g_rx<2>(ar, ai, trc[lb + 6],  trs[lb + 6]);
            g_ry<2>(ar, ai, trc[lb + 7],  trs[lb + 7]);
            g_rz<2>(ar, ai, trc[lb + 8],  trs[lb + 8]);
            g_rx<1>(ar, ai, trc[lb + 9],  trs[lb + 9]);
            g_ry<1>(ar, ai, trc[lb + 10], trs[lb + 10]);
            g_rz<1>(ar, ai, trc[lb + 11], trs[lb + 11]);
            g_cnot<8, 4>(ar, ai);
            g_cnot<4, 2>(ar, ai);
            g_cnot<2, 1>(ar, ai);
            g_cnot<1, 8>(ar, ai);
        }
#pragma unroll
        for (int k = 0; k < 16; k++) { Ur[br][k][col] = ar[k]; Ui[br][k][col] = ai[k]; }
    }
    __syncthreads();
#pragma unroll
    for (int e = 0; e < 2; e++) {
        const int idx = e * 256 + tid;                 // 0..511
        const int br = idx >> 8, rem2 = idx & 255;
        const int i = rem2 >> 4, j = rem2 & 15;
        float s = 0.f;
#pragma unroll
        for (int k = 0; k < 16; k++) {
            const float z = (k & 8) ? -1.f : 1.f;
            s += z * (Ur[br][k][i] * Ur[br][k][j] + Ui[br][k][i] * Ui[br][k][j]);
        }
        g_A[br][i][j] = s;
    }
}

// ---------------- main kernel (persistent, balanced partition, fp16-acc mainloop) ----
__global__ __launch_bounds__(NT, 2)
void qmain(const float* __restrict__ state, const float* __restrict__ action,
           const float* __restrict__ b1a, const float* __restrict__ W2a, const float* __restrict__ b2a,
           const float* __restrict__ b1b, const float* __restrict__ W2b, const float* __restrict__ b2b,
           const float* __restrict__ pwa, const float* __restrict__ pba,
           const float* __restrict__ pwb, const float* __restrict__ pbb,
           float* __restrict__ out, int Btot)
{
    extern __shared__ __align__(16) unsigned char smp[];
    float* smf = (float*)smp;
    __half* Ah = (__half*)(smp + OFF_A);
    float* qin = smf + OFF_QIN / 4;
    const uint32_t smb = smem_u32(smp);

    const int tid = threadIdx.x;
    const int lane = tid & 31, w = tid >> 5;
    const int gid = lane >> 2, tig = lane & 3;
    const int wm = w & 3, wn = w >> 2;
    const int m0 = wm * 32, n0 = wn * 32;
    const int ntiles = Btot / TB;

    const int G = gridDim.x;
    const int base = ntiles / G, rem = ntiles % G;
    const int bid = blockIdx.x;
    const int cnt = base + (bid < rem ? 1 : 0);
    const int start = bid * base + (bid < rem ? bid : rem);

    // ---- kick off B load for pass 0 (buf 0) ----
    {
        const char* sH = (const char*)&g_W1h[0][0][0];
        for (int i = tid; i < BCH / 16; i += NT)
            CPA16(smb + OFF_B + i * 16, sH + i * 16);
        CPA_COMMIT();
    }

    // ---- params into smem (once per CTA) ----
    for (int i = tid; i < 512; i += NT)
        smf[OFF_B1 / 4 + i] = ((i >> 8) ? b1b : b1a)[i & 255];
    for (int i = tid; i < 1024; i += NT) {
        const int br = i >> 9, g = (i >> 5) & 15, ln = i & 31;
        const int gq = ln >> 2, gt = ln & 3;
        const int kc = g * 16 + 2 * gt;
        const float* W2 = br ? W2b : W2a;
        uint32_t r0 = 0, r1 = 0;
        if (gq < 4) {
            r0 = h2u(W2[gq * 256 + kc],     W2[gq * 256 + kc + 1]);
            r1 = h2u(W2[gq * 256 + kc + 8], W2[gq * 256 + kc + 9]);
        }
        ((uint2*)(smp + OFF_W2F))[i] = make_uint2(r0, r1);
    }
    if (tid < 8)  smf[OFF_B2 / 4 + tid] = ((tid >> 2) ? b2b : b2a)[tid & 3];
    for (int i = tid; i < 512; i += NT)
        smf[OFF_A16 / 4 + i] = ((const float*)g_A)[i];
    if (tid < 4)
        smf[OFF_PP / 4 + tid] = (tid == 0) ? pwa[0] : (tid == 1) ? pba[0]
                               : (tid == 2) ? pwb[0] : pbb[0];
    for (int i = tid; i < 1024; i += NT) qin[i] = 0.f;

    // ---- ldmatrix byte-address bases ----
    const uint32_t aB0 = smb + OFF_A
        + (uint32_t)((m0 + (lane & 15)) * RS + 8 * (lane >> 4)) * 2;
    const uint32_t aB1 = aB0 + 16u * RS * 2;
    const uint32_t bO0 = (uint32_t)((n0 + 8 * (lane >> 4) + (lane & 7)) * RS
                                    + 8 * ((lane >> 3) & 1)) * 2;
    const uint32_t bO1 = bO0 + 16u * RS * 2;

    // q partial accumulators (tensor-core epilogue, f32), per mf fragment
    float qacc[2][4];
#pragma unroll
    for (int mf = 0; mf < 2; mf++)
#pragma unroll
        for (int c = 0; c < 4; c++) qacc[mf][c] = 0.f;

    // ================= persistent tile loop =================
    for (int t = 0; t < cnt; t++) {
        const int tile = start + t;
        const int rowg0 = tile * TB;
        const bool last_tile = (t == cnt - 1);

        // ---- x -> fp16 A tile [row][k], stride RS ----
        {
            const int r = tid >> 1, hf = tid & 1;
            const float* srow = state  + (size_t)(rowg0 + r) * 128;
            const float* arow = action + (size_t)(rowg0 + r) * 32;
#pragma unroll 5
            for (int i = 0; i < 20; i++) {
                const int k = hf * 80 + i * 4;
                const float4 v = (k < 128) ? *(const float4*)(srow + k)
                                           : *(const float4*)(arow + (k - 128));
                *(__half2*)(Ah + r * RS + k)     = __floats2half2_rn(v.x, v.y);
                *(__half2*)(Ah + r * RS + k + 2) = __floats2half2_rn(v.z, v.w);
            }
        }
        __syncthreads();   // A ready (also orders epilogue qin-zero vs flushes)

#pragma unroll 1
        for (int pass = 0; pass < 8; pass++) {
            const int br = pass >> 2, chunk = pass & 3;
            const int nbase = chunk * 64;
            const int buf = pass & 1;

            // prefetch next pass ((pass+1) mod 8 — tile-invariant sequence)
            if (!(last_tile && pass == 7)) {
                const int pN = (pass + 1) & 7;
                const char* sH = (const char*)&g_W1h[pN >> 2][(pN & 3) * 64][0];
                const uint32_t dst = smb + OFF_B + (uint32_t)(pN & 1) * BCH;
                for (int i = tid; i < BCH / 16; i += NT)
                    CPA16(dst + i * 16, sH + i * 16);
                CPA_COMMIT();
                CPA_WAIT1();
            } else {
                CPA_WAIT0();
            }
            __syncthreads();

            const uint32_t bB = smb + OFF_B + (uint32_t)buf * BCH;

            // fp16 packed accumulators: [mf][nf] -> {row gid cols 2tig..+1, row gid+8}
            uint32_t accH[2][4][2];
#pragma unroll
            for (int mf = 0; mf < 2; mf++)
#pragma unroll
                for (int nf = 0; nf < 4; nf++) { accH[mf][nf][0] = 0; accH[mf][nf][1] = 0; }

#pragma unroll
            for (int ks = 0; ks < 10; ks++) {
                const uint32_t kb = (uint32_t)(ks * 32);   // 16 elem * 2B
                uint32_t af[2][4], bf[2][4];
                ldsm4(af[0], aB0 + kb);
                ldsm4(af[1], aB1 + kb);
                ldsm4(bf[0], bB + bO0 + kb);
                ldsm4(bf[1], bB + bO1 + kb);
#pragma unroll
                for (int g = 0; g < 2; g++)
#pragma unroll
                    for (int h = 0; h < 2; h++)
#pragma unroll
                        for (int mf = 0; mf < 2; mf++)
                            mma_f16h(accH[mf][g * 2 + h], af[mf], bf[g][h * 2], bf[g][h * 2 + 1]);
            }

            // ---- tensor-core epilogue: unpack + bias+relu -> fp16 frags -> MMA vs W2 ----
            {
                const float2* b1v = (const float2*)(smf + OFF_B1 / 4 + br * 256);
                const uint2* w2f = (const uint2*)(smp + OFF_W2F);
                const int gbase = (nbase + n0) >> 4;
                const uint2 bfA = w2f[(((br << 4) + gbase) << 5) + lane];
                const uint2 bfB = w2f[(((br << 4) + gbase + 1) << 5) + lane];
#pragma unroll
                for (int ks = 0; ks < 2; ks++) {
                    const int nfa = ks * 2, nfb = nfa + 1;
                    const float2 bba = b1v[((nbase + n0 + nfa * 8) >> 1) + tig];
                    const float2 bbb = b1v[((nbase + n0 + nfb * 8) >> 1) + tig];
                    const uint2 bfr = ks ? bfB : bfA;
#pragma unroll
                    for (int mf = 0; mf < 2; mf++) {
                        const float2 va = __half22float2(*(const __half2*)&accH[mf][nfa][0]);
                        const float2 vb = __half22float2(*(const __half2*)&accH[mf][nfa][1]);
                        const float2 vc = __half22float2(*(const __half2*)&accH[mf][nfb][0]);
                        const float2 vd = __half22float2(*(const __half2*)&accH[mf][nfb][1]);
                        const uint32_t a0 = h2u(fmaxf(va.x + bba.x, 0.f),
                                                fmaxf(va.y + bba.y, 0.f));
                        const uint32_t a1 = h2u(fmaxf(vb.x + bba.x, 0.f),
                                                fmaxf(vb.y + bba.y, 0.f));
                        const uint32_t a2 = h2u(fmaxf(vc.x + bbb.x, 0.f),
                                                fmaxf(vc.y + bbb.y, 0.f));
                        const uint32_t a3 = h2u(fmaxf(vd.x + bbb.x, 0.f),
                                                fmaxf(vd.y + bbb.y, 0.f));
                        mma_f16u(qacc[mf], a0, a1, a2, a3, bfr.x, bfr.y);
                    }
                }
            }

            // flush q partials at branch boundary
            if (chunk == 3) {
                if (tig < 2) {
                    const int qb = 2 * tig;
#pragma unroll
                    for (int mf = 0; mf < 2; mf++) {
                        float* q0 = qin + ((br << 7) + m0 + mf * 16 + gid) * 4 + qb;
                        float* q1 = qin + ((br << 7) + m0 + mf * 16 + gid + 8) * 4 + qb;
                        atomicAdd(q0,     qacc[mf][0]);
                        atomicAdd(q0 + 1, qacc[mf][1]);
                        atomicAdd(q1,     qacc[mf][2]);
                        atomicAdd(q1 + 1, qacc[mf][3]);
                    }
                }
#pragma unroll
                for (int mf = 0; mf < 2; mf++)
#pragma unroll
                    for (int c = 0; c < 4; c++) qacc[mf][c] = 0.f;
            }

            __syncthreads();   // all reads of buf done before overwrite
        }

        // ---- quadratic-form epilogue: 1 row/thread, 128 rows x 2 branches ----
        {
            const int br = tid >> 7, row = tid & 127;
            const float* b2s = smf + OFF_B2 / 4 + br * 4;
            const float* Ab = smf + OFF_A16 / 4 + br * 256;
            const float pw = smf[OFF_PP / 4 + br * 2];
            const float pb = smf[OFF_PP / 4 + br * 2 + 1];
            float* qv = qin + ((br << 7) + row) * 4;

            float c[4], s[4];
#pragma unroll
            for (int q = 0; q < 4; q++) {
                sincosf(0.5f * (qv[q] + b2s[q]), &s[q], &c[q]);
                qv[q] = 0.f;    // reset for next tile (ordered by next A-sync)
            }

            float p01[4] = {c[0] * c[1], c[0] * s[1], s[0] * c[1], s[0] * s[1]};
            float p23[4] = {c[2] * c[3], c[2] * s[3], s[2] * c[3], s[2] * s[3]};
            float v[16];
#pragma unroll
            for (int hi = 0; hi < 4; hi++)
#pragma unroll
                for (int lo = 0; lo < 4; lo++)
                    v[hi * 4 + lo] = p01[hi] * p23[lo];

            float ev = 0.f;
#pragma unroll
            for (int i = 0; i < 16; i++) {
                const float4* Ar = (const float4*)(Ab + i * 16);
                float wi = 0.f;
#pragma unroll
                for (int j4 = 0; j4 < 4; j4++) {
                    const float4 a4 = Ar[j4];
                    wi = fmaf(a4.x, v[j4 * 4 + 0], wi);
                    wi = fmaf(a4.y, v[j4 * 4 + 1], wi);
                    wi = fmaf(a4.z, v[j4 * 4 + 2], wi);
                    wi = fmaf(a4.w, v[j4 * 4 + 3], wi);
                }
                ev = fmaf(v[i], wi, ev);
            }
            out[(size_t)br * Btot + rowg0 + row] = fmaf(ev, pw, pb);
        }
    }
}

extern "C" void kernel_launch(void* const* d_in, const int* in_sizes, int n_in,
                              void* d_out, int out_size)
{
    const int Btot = in_sizes[0] / 128;
    const int ntiles = Btot / TB;
    const int grid = (ntiles < GRID_P) ? ntiles : GRID_P;
    static bool attr_set = false;
    if (!attr_set) {
        cudaFuncSetAttribute(qmain, cudaFuncAttributeMaxDynamicSharedMemorySize, SMEM_BYTES);
        attr_set = true;
    }
    qpre<<<81, 256>>>((const float*)d_in[2], (const float*)d_in[6],
                      (const float*)d_in[10], (const float*)d_in[11]);
    qmain<<<grid, NT, SMEM_BYTES>>>(
        (const float*)d_in[0],  (const float*)d_in[1],
        (const float*)d_in[3],  (const float*)d_in[4],  (const float*)d_in[5],
        (const float*)d_in[7],  (const float*)d_in[8],  (const float*)d_in[9],
        (const float*)d_in[12], (const float*)d_in[13],
        (const float*)d_in[14], (const float*)d_in[15],
        (float*)d_out, Btot);
}